// round 15
// baseline (speedup 1.0000x reference)
#include <cuda_runtime.h>
#include <cuda_fp16.h>
#include <math.h>
#include <stdint.h>

#define BATCH 2
#define SEQ   2048
#define NH    12
#define HD    64
#define EMB   768     // NH*HD
#define PLMD  1280
#define SD    128
#define FFD   640
#define ROWS  (BATCH*SEQ)                 // 4096
#define BH    (BATCH*NH)                  // 24
#define OUT_ELEMS ((long)ROWS*PLMD)       // 5,242,880
#define LOG2_10000 13.287712379549449f

// ---------------- scratch (static __device__, no allocation) ----------------
__device__ __align__(16) float g_qp[ROWS*EMB];
__device__ __align__(16) float g_kp[ROWS*EMB];
__device__ __align__(16) float g_vp[ROWS*EMB];
__device__ __align__(16) float g_vals[ROWS*EMB]; // [B,S,E]
__device__ __align__(16) float g_x[ROWS*PLMD];
__device__ __align__(16) float g_ln[ROWS*PLMD];
__device__ __align__(16) float g_ff[ROWS*FFD];
__device__ __align__(16) float g_cos[SEQ*32];
__device__ __align__(16) float g_sin[SEQ*32];
__device__ __align__(16) float g_psum[BH*16*SEQ];  // [bh][colblk][row]
__device__ __align__(16) float g_rinv[BH*SEQ];
__device__ __align__(16) __half g_eh[100663296];   // BH*SEQ*SEQ fp16 exp values
__device__ __align__(16) __half g_vth[ROWS*EMB];   // [BH,D,S] fp16 V^T

// ---------------- helpers ----------------
__device__ __forceinline__ uint32_t f2tf32(uint32_t xbits) {
    uint32_t u;
    float f = __uint_as_float(xbits);
    asm("cvt.rna.tf32.f32 %0, %1;" : "=r"(u) : "f"(f));
    return u;
}
__device__ __forceinline__ uint32_t f2tf32f(float f) {
    uint32_t u;
    asm("cvt.rna.tf32.f32 %0, %1;" : "=r"(u) : "f"(f));
    return u;
}

__device__ __forceinline__ void mma_tf32(float* c, const uint32_t* a, const uint32_t* b) {
    asm volatile("mma.sync.aligned.m16n8k8.row.col.f32.tf32.tf32.f32 "
        "{%0,%1,%2,%3}, {%4,%5,%6,%7}, {%8,%9}, {%0,%1,%2,%3};"
        : "+f"(c[0]), "+f"(c[1]), "+f"(c[2]), "+f"(c[3])
        : "r"(a[0]), "r"(a[1]), "r"(a[2]), "r"(a[3]), "r"(b[0]), "r"(b[1]));
}

__device__ __forceinline__ void cp_async16(uint32_t smem_dst, const void* gsrc) {
    asm volatile("cp.async.cg.shared.global [%0], [%1], 16;" :: "r"(smem_dst), "l"(gsrc));
}
__device__ __forceinline__ void cp_commit() { asm volatile("cp.async.commit_group;"); }
__device__ __forceinline__ void cp_wait1()  { asm volatile("cp.async.wait_group 1;"); }

// ---------------- RoPE cos/sin tables ----------------
__global__ void rope_table_kernel() {
    int idx = blockIdx.x * blockDim.x + threadIdx.x;
    if (idx >= SEQ*32) return;
    int s = idx >> 5, j = idx & 31;
    float inv = exp2f(-(float)j * (LOG2_10000 / 32.0f));
    float freq = (float)s * inv;
    float sn, c;
    sincosf(freq, &sn, &c);
    g_cos[idx] = c; g_sin[idx] = sn;
}

// ---------------- TF32 pipelined GEMM: C = A@B^T (+bias)(+extra)(gelu) ----
template<int EPI, int BM, int BN, int WARPS_M, int WARPS_N>
__global__ __launch_bounds__(256)
void gemm_tf32(const float* __restrict__ A, const float* __restrict__ B,
               const float* __restrict__ bias, const float* __restrict__ extra,
               float* __restrict__ C,
               int K, int sAm, int sBn, int ldc)
{
    constexpr int BK   = 32;
    constexpr int LDSW = 36;
    constexpr int WM = BM / WARPS_M, WN = BN / WARPS_N;
    constexpr int MF = WM / 16, NF = WN / 8;
    constexpr int ASTG = BM * LDSW;
    constexpr int BSTG = BN * LDSW;

    extern __shared__ uint32_t smem[];
    uint32_t* As = smem;
    uint32_t* Bs = smem + 2 * ASTG;

    const int tid  = threadIdx.x;
    const int lane = tid & 31;
    const int warp = tid >> 5;
    const int wm = warp % WARPS_M, wn = warp / WARPS_M;
    const int row0 = blockIdx.y * BM, col0 = blockIdx.x * BN;
    A += (long)row0 * sAm;
    B += (long)col0 * sBn;

    const uint32_t smem_base = (uint32_t)__cvta_generic_to_shared(smem);
    const int r  = lane >> 2;
    const int cq = lane & 3;

    float acc[MF][NF][4];
#pragma unroll
    for (int m = 0; m < MF; m++)
#pragma unroll
        for (int n = 0; n < NF; n++)
#pragma unroll
            for (int j = 0; j < 4; j++) acc[m][n][j] = 0.f;

    const int lrow = tid >> 3;
    const int lf   = (tid & 7) * 4;

    auto prefetch = [&](int stage, int k0) {
#pragma unroll
        for (int i = 0; i < BM/32; i++) {
            int row = lrow + i*32;
            cp_async16(smem_base + (stage*ASTG + row*LDSW + lf)*4,
                       A + (long)row*sAm + k0 + lf);
        }
#pragma unroll
        for (int i = 0; i < BN/32; i++) {
            int row = lrow + i*32;
            cp_async16(smem_base + ((2*ASTG) + stage*BSTG + row*LDSW + lf)*4,
                       B + (long)row*sBn + k0 + lf);
        }
    };

    const int nk = K / BK;
    prefetch(0, 0);
    cp_commit();

    for (int kt = 0; kt < nk; kt++) {
        const int stage = kt & 1;
        if (kt + 1 < nk) prefetch(stage ^ 1, (kt+1) * BK);
        cp_commit();
        cp_wait1();
        __syncthreads();

        const uint32_t* Ast = As + stage * ASTG;
        const uint32_t* Bst = Bs + stage * BSTG;
#pragma unroll
        for (int ks = 0; ks < BK/8; ks++) {
            const int kk = ks * 8;
            uint32_t af[MF][4], bf[NF][2];
#pragma unroll
            for (int m = 0; m < MF; m++) {
                int base = (wm*WM + m*16 + r)*LDSW + kk + cq;
                af[m][0] = f2tf32(Ast[base]);
                af[m][1] = f2tf32(Ast[base + 8*LDSW]);
                af[m][2] = f2tf32(Ast[base + 4]);
                af[m][3] = f2tf32(Ast[base + 8*LDSW + 4]);
            }
#pragma unroll
            for (int n = 0; n < NF; n++) {
                int base = (wn*WN + n*8 + r)*LDSW + kk + cq;
                bf[n][0] = f2tf32(Bst[base]);
                bf[n][1] = f2tf32(Bst[base + 4]);
            }
#pragma unroll
            for (int m = 0; m < MF; m++)
#pragma unroll
                for (int n = 0; n < NF; n++)
                    mma_tf32(acc[m][n], af[m], bf[n]);
        }
        __syncthreads();
    }

#pragma unroll
    for (int m = 0; m < MF; m++) {
#pragma unroll
        for (int n = 0; n < NF; n++) {
            int row = row0 + wm*WM + m*16 + r;
            int col = col0 + wn*WN + n*8 + 2*cq;
            float v0 = acc[m][n][0];
            float v1 = acc[m][n][1];
            float v2 = acc[m][n][2];
            float v3 = acc[m][n][3];
            if (bias) { v0 += bias[col]; v1 += bias[col+1]; v2 += bias[col]; v3 += bias[col+1]; }
            if (EPI == 1) {
                v0 += extra[(long)row*ldc + col];
                v1 += extra[(long)row*ldc + col + 1];
                v2 += extra[(long)(row+8)*ldc + col];
                v3 += extra[(long)(row+8)*ldc + col + 1];
            }
            if (EPI == 2) {
                v0 = 0.5f * v0 * (1.f + erff(v0 * 0.70710678118654752f));
                v1 = 0.5f * v1 * (1.f + erff(v1 * 0.70710678118654752f));
                v2 = 0.5f * v2 * (1.f + erff(v2 * 0.70710678118654752f));
                v3 = 0.5f * v3 * (1.f + erff(v3 * 0.70710678118654752f));
            }
            *reinterpret_cast<float2*>(&C[(long)row*ldc + col])     = make_float2(v0, v1);
            *reinterpret_cast<float2*>(&C[(long)(row+8)*ldc + col]) = make_float2(v2, v3);
        }
    }
}

// ---------------- QK^T fused RoPE: E = exp(s/8) fp16 (coalesced) + sums -----
#define LDE 136     // halfs per Eh row
__global__ __launch_bounds__(256)
void qk_rope_exp_kernel(const float* __restrict__ qp, const float* __restrict__ kp)
{
    constexpr int LDSW = 68;
    extern __shared__ float sm[];
    float* Qs = sm;                 // [128*LDSW]
    float* Ks = sm + 128*LDSW;

    const int tid  = threadIdx.x;
    const int lane = tid & 31;
    const int warp = tid >> 5;
    const int wm = warp & 1, wn = warp >> 1;   // 2 x 4 warps
    const int bh = blockIdx.z;
    const int b = bh / NH, h = bh % NH;
    const int row0 = blockIdx.y * 128, col0 = blockIdx.x * 128;

    const float* qb = qp + (long)b*SEQ*EMB + h*HD;
    const float* kb = kp + (long)b*SEQ*EMB + h*HD;

#pragma unroll
    for (int i = 0; i < 8; i++) {
        int idx = tid + i*256;
        int rr = idx >> 4, f = idx & 15;
        int d0 = f*4;
        int j0 = d0 & 31;
        float sgn = (d0 < 32) ? -1.f : 1.f;
        {   // Q
            int s = row0 + rr;
            float4 x  = *reinterpret_cast<const float4*>(qb + (long)s*EMB + d0);
            float4 p  = *reinterpret_cast<const float4*>(qb + (long)s*EMB + (d0 ^ 32));
            float4 c  = *reinterpret_cast<const float4*>(&g_cos[s*32 + j0]);
            float4 sn = *reinterpret_cast<const float4*>(&g_sin[s*32 + j0]);
            float4 o;
            o.x = x.x*c.x + sgn*p.x*sn.x;
            o.y = x.y*c.y + sgn*p.y*sn.y;
            o.z = x.z*c.z + sgn*p.z*sn.z;
            o.w = x.w*c.w + sgn*p.w*sn.w;
            *reinterpret_cast<float4*>(&Qs[rr*LDSW + d0]) = o;
        }
        {   // K
            int s = col0 + rr;
            float4 x  = *reinterpret_cast<const float4*>(kb + (long)s*EMB + d0);
            float4 p  = *reinterpret_cast<const float4*>(kb + (long)s*EMB + (d0 ^ 32));
            float4 c  = *reinterpret_cast<const float4*>(&g_cos[s*32 + j0]);
            float4 sn = *reinterpret_cast<const float4*>(&g_sin[s*32 + j0]);
            float4 o;
            o.x = x.x*c.x + sgn*p.x*sn.x;
            o.y = x.y*c.y + sgn*p.y*sn.y;
            o.z = x.z*c.z + sgn*p.z*sn.z;
            o.w = x.w*c.w + sgn*p.w*sn.w;
            *reinterpret_cast<float4*>(&Ks[rr*LDSW + d0]) = o;
        }
    }
    __syncthreads();

    const int r  = lane >> 2;
    const int cq = lane & 3;
    float acc[4][4][4];
#pragma unroll
    for (int m = 0; m < 4; m++)
#pragma unroll
        for (int n = 0; n < 4; n++)
#pragma unroll
            for (int j = 0; j < 4; j++) acc[m][n][j] = 0.f;

#pragma unroll
    for (int ks = 0; ks < 8; ks++) {
        const int kk = ks * 8;
        uint32_t af[4][4], bf[4][2];
#pragma unroll
        for (int m = 0; m < 4; m++) {
            int base = (wm*64 + m*16 + r)*LDSW + kk + cq;
            af[m][0] = f2tf32f(Qs[base]);
            af[m][1] = f2tf32f(Qs[base + 8*LDSW]);
            af[m][2] = f2tf32f(Qs[base + 4]);
            af[m][3] = f2tf32f(Qs[base + 8*LDSW + 4]);
        }
#pragma unroll
        for (int n = 0; n < 4; n++) {
            int base = (wn*32 + n*8 + r)*LDSW + kk + cq;
            bf[n][0] = f2tf32f(Ks[base]);
            bf[n][1] = f2tf32f(Ks[base + 4]);
        }
#pragma unroll
        for (int m = 0; m < 4; m++)
#pragma unroll
            for (int n = 0; n < 4; n++)
                mma_tf32(acc[m][n], af[m], bf[n]);
    }

    // exp(s * 0.125) — the only exp pass in the whole pipeline
#pragma unroll
    for (int m = 0; m < 4; m++)
#pragma unroll
        for (int n = 0; n < 4; n++)
#pragma unroll
            for (int j = 0; j < 4; j++)
                acc[m][n][j] = __expf(acc[m][n][j] * 0.125f);

    // ---- stage E into SMEM (fp16) + write partial sums ----
    __syncthreads();              // Qs/Ks dead; reuse as Eh + Sred
    __half* Eh = reinterpret_cast<__half*>(sm);         // [128][LDE]
    float* Sred = sm + (128*LDE)/2;                     // [128][17]
    const int slot = wn*4 + cq;

#pragma unroll
    for (int m = 0; m < 4; m++) {
#pragma unroll
        for (int n = 0; n < 4; n++) {
            int row = wm*64 + m*16 + r;
            int col = wn*32 + n*8 + 2*cq;
            *reinterpret_cast<__half2*>(&Eh[row*LDE + col]) =
                __floats2half2_rn(acc[m][n][0], acc[m][n][1]);
            *reinterpret_cast<__half2*>(&Eh[(row+8)*LDE + col]) =
                __floats2half2_rn(acc[m][n][2], acc[m][n][3]);
        }
    }
#pragma unroll
    for (int m = 0; m < 4; m++)
#pragma unroll
        for (int hf = 0; hf < 2; hf++) {
            int rl = wm*64 + m*16 + r + hf*8;
            float s = 0.f;
#pragma unroll
            for (int n = 0; n < 4; n++)
                s += acc[m][n][hf*2] + acc[m][n][hf*2+1];
            Sred[rl*17 + slot] = s;
        }
    __syncthreads();

    // ---- coalesced fp16 store: 2 threads per row, interleaved 16B chunks ----
    __half* Eb = g_eh + (long)bh*SEQ*SEQ;
    {
        int row = tid >> 1;
        long gbase = (long)(row0 + row)*SEQ + col0;
#pragma unroll
        for (int j = 0; j < 8; j++) {
            int ho = ((tid & 1) + 2*j) * 8;
            uint4 v = *reinterpret_cast<const uint4*>(&Eh[row*LDE + ho]);
            __stcs(reinterpret_cast<uint4*>(Eb + gbase + ho), v);
        }
    }
    if (tid < 128) {
        float s = 0.f;
#pragma unroll
        for (int i = 0; i < 16; i++) s += Sred[tid*17 + i];
        g_psum[(long)(bh*16 + blockIdx.x)*SEQ + row0 + tid] = s;
    }
}

// ---------------- reduce 16 partials per row -> 1/sum ----------------
__global__ __launch_bounds__(256)
void reduce_stats_kernel()
{
    int rg = blockIdx.x * 256 + threadIdx.x;
    if (rg >= BH*SEQ) return;
    int bh = rg >> 11, row = rg & (SEQ-1);
    long base = (long)bh*16*SEQ + row;
    float s = 0.f;
#pragma unroll
    for (int i = 0; i < 16; i++) s += g_psum[base + (long)i*SEQ];
    g_rinv[rg] = 1.f / s;
}

// ---------------- AV on fp16 E and fp16 V^T: probs (fp32) + merged O --------
// BM=64, BK=64 -> grid (1, 32, 24) = 768 blocks, ~37KB SMEM.
#define AVLD 72   // halfs per SMEM row (64 + 8 pad)
__global__ __launch_bounds__(256)
void av_half_kernel(float* __restrict__ attn, float* __restrict__ vals)
{
    extern __shared__ float smf[];
    __half* Ah = reinterpret_cast<__half*>(smf);          // [2][64*AVLD]
    __half* Bh = Ah + 2*64*AVLD;                          // [2][64*AVLD]
    float*  rinv_s = smf + (4*64*AVLD)/2;                 // [64]

    const int tid  = threadIdx.x;
    const int lane = tid & 31;
    const int warp = tid >> 5;
    const int wm = warp & 1, wn = warp >> 1;   // 2 x 4 -> warp tile 32x16
    const int bh = blockIdx.z;
    const int b = bh / NH, h = bh % NH;
    const int row0 = blockIdx.y * 64;
    const int r  = lane >> 2;
    const int cq = lane & 3;

    const __half* Eb = g_eh + (long)bh*SEQ*SEQ + (long)row0*SEQ;
    const __half* Vb = g_vth + (long)bh*HD*SEQ;
    float* Ab = attn + (long)bh*SEQ*SEQ + (long)row0*SEQ;

    if (tid < 64) rinv_s[tid] = g_rinv[bh*SEQ + row0 + tid];

    const uint32_t a_base = (uint32_t)__cvta_generic_to_shared(Ah);
    const uint32_t b_base = (uint32_t)__cvta_generic_to_shared(Bh);

    auto prefetch = [&](int stage, int k0) {
#pragma unroll
        for (int i = 0; i < 2; i++) {
            int idx = tid + i*256;
            int row = idx >> 3, ch = (idx & 7) * 8;
            cp_async16(a_base + (stage*64*AVLD + row*AVLD + ch)*2,
                       Eb + (long)row*SEQ + k0 + ch);
            cp_async16(b_base + (stage*64*AVLD + row*AVLD + ch)*2,
                       Vb + (long)row*SEQ + k0 + ch);
        }
    };

    float acc[2][2][4];
#pragma unroll
    for (int m = 0; m < 2; m++)
#pragma unroll
        for (int n = 0; n < 2; n++)
#pragma unroll
            for (int j = 0; j < 4; j++) acc[m][n][j] = 0.f;

    prefetch(0, 0);
    cp_commit();

    for (int kt = 0; kt < 32; kt++) {
        const int stage = kt & 1;
        if (kt + 1 < 32) prefetch(stage ^ 1, (kt+1) * 64);
        cp_commit();
        cp_wait1();
        __syncthreads();

        const __half* Ast = Ah + stage*64*AVLD;
        const __half* Bst = Bh + stage*64*AVLD;

        // ---- coalesced prob store: 16 threads/row x float4 = 256B runs ----
#pragma unroll
        for (int g = 0; g < 4; g++) {
            int row  = g*16 + (tid >> 4);
            int colf = (tid & 15) * 4;
            __half2 h01 = *reinterpret_cast<const __half2*>(&Ast[row*AVLD + colf]);
            __half2 h23 = *reinterpret_cast<const __half2*>(&Ast[row*AVLD + colf + 2]);
            float riv = rinv_s[row];
            float4 o;
            o.x = __low2float(h01)  * riv;
            o.y = __high2float(h01) * riv;
            o.z = __low2float(h23)  * riv;
            o.w = __high2float(h23) * riv;
            __stcs(reinterpret_cast<float4*>(Ab + (long)row*SEQ + kt*64 + colf), o);
        }

        // ---- MMA on raw E / raw V (both fp16->tf32) ----
#pragma unroll
        for (int ks = 0; ks < 8; ks++) {
            const int kk = ks * 8;
            uint32_t af[2][4], bf[2][2];
#pragma unroll
            for (int m = 0; m < 2; m++) {
                int base = (wm*32 + m*16 + r)*AVLD + kk + cq;
                af[m][0] = f2tf32f(__half2float(Ast[base]));
                af[m][1] = f2tf32f(__half2float(Ast[base + 8*AVLD]));
                af[m][2] = f2tf32f(__half2float(Ast[base + 4]));
                af[m][3] = f2tf32f(__half2float(Ast[base + 8*AVLD + 4]));
            }
#pragma unroll
            for (int n = 0; n < 2; n++) {
                int base = (wn*16 + n*8 + r)*AVLD + kk + cq;
                bf[n][0] = f2tf32f(__half2float(Bst[base]));
                bf[n][1] = f2tf32f(__half2float(Bst[base + 4]));
            }
#pragma unroll
            for (int m = 0; m < 2; m++)
#pragma unroll
                for (int n = 0; n < 2; n++)
                    mma_tf32(acc[m][n], af[m], bf[n]);
        }
        __syncthreads();
    }

    // epilogue: scale O rows by rinv, write merged [B,S,H*D]
#pragma unroll
    for (int m = 0; m < 2; m++) {
        int lr = wm*32 + m*16 + r;
        float s0 = rinv_s[lr], s1 = rinv_s[lr + 8];
#pragma unroll
        for (int n = 0; n < 2; n++) {
            int srow = row0 + lr;
            int col  = h*HD + wn*16 + n*8 + 2*cq;
            *reinterpret_cast<float2*>(&vals[(long)(b*SEQ + srow)*EMB + col]) =
                make_float2(acc[m][n][0]*s0, acc[m][n][1]*s0);
            *reinterpret_cast<float2*>(&vals[(long)(b*SEQ + srow + 8)*EMB + col]) =
                make_float2(acc[m][n][2]*s1, acc[m][n][3]*s1);
        }
    }
}

// ---------------- V transpose (tiled): [B,S,H*D] -> [BH,D,S] fp16 -----------
__global__ __launch_bounds__(256)
void v_transpose_kernel(const float* __restrict__ src, __half* __restrict__ dst)
{
    __shared__ float t[32][33];
    const int bh = blockIdx.z;
    const int b = bh / NH, h = bh % NH;
    const int d0 = blockIdx.y * 32;
    const int s0 = blockIdx.x * 32;
    const int col = threadIdx.x & 31;
    const int rw  = threadIdx.x >> 5;
#pragma unroll
    for (int i = 0; i < 4; i++) {
        int row = rw + i*8;
        t[row][col] = src[(long)(b*SEQ + s0 + row)*EMB + h*HD + d0 + col];
    }
    __syncthreads();
#pragma unroll
    for (int i = 0; i < 4; i++) {
        int d = rw + i*8;
        dst[((long)bh*HD + d0 + d)*SEQ + s0 + col] = __float2half_rn(t[col][d]);
    }
}

// ---------------- LayerNorm over 1280 ----------------
__global__ __launch_bounds__(256) void layernorm_kernel(const float* __restrict__ x,
    const float* __restrict__ g, const float* __restrict__ b, float* __restrict__ y)
{
    __shared__ float buf[PLMD];
    __shared__ float red[256];
    long row = blockIdx.x;
    const float* xr = x + row*PLMD;
    int tid = threadIdx.x;
    float s = 0.f;
    for (int i = tid; i < PLMD; i += 256) { float t = xr[i]; buf[i] = t; s += t; }
    red[tid] = s; __syncthreads();
    for (int st = 128; st > 0; st >>= 1) { if (tid < st) red[tid] += red[tid+st]; __syncthreads(); }
    float mu = red[0] * (1.f/PLMD); __syncthreads();
    float vs = 0.f;
    for (int i = tid; i < PLMD; i += 256) { float d = buf[i] - mu; vs += d*d; }
    red[tid] = vs; __syncthreads();
    for (int st = 128; st > 0; st >>= 1) { if (tid < st) red[tid] += red[tid+st]; __syncthreads(); }
    float rstd = rsqrtf(red[0] * (1.f/PLMD) + 1e-5f);
    float* yr = y + row*PLMD;
    for (int i = tid; i < PLMD; i += 256) yr[i] = (buf[i] - mu) * rstd * g[i] + b[i];
}

// ---------------- launch ----------------
extern "C" void kernel_launch(void* const* d_in, const int* in_sizes, int n_in,
                              void* d_out, int out_size)
{
    const float* s_repre = (const float*)d_in[0];
    const float* plm     = (const float*)d_in[1];
    const float* Wq = (const float*)d_in[2];  const float* bq = (const float*)d_in[3];
    const float* Wk = (const float*)d_in[4];  const float* bk = (const float*)d_in[5];
    const float* Wv = (const float*)d_in[6];  const float* bv = (const float*)d_in[7];
    const float* Wo = (const float*)d_in[8];  const float* bo = (const float*)d_in[9];
    const float* lng = (const float*)d_in[10]; const float* lnb = (const float*)d_in[11];
    const float* Wd = (const float*)d_in[12]; const float* bd = (const float*)d_in[13];
    const float* Wu = (const float*)d_in[14]; const float* bu = (const float*)d_in[15];

    float* out  = (float*)d_out;
    float* attn = out + OUT_ELEMS;   // tuple order: (out, attention)

    float *qp,*kp,*vp,*vals,*x,*ln,*ff;
    __half* vth;
    cudaGetSymbolAddress((void**)&qp, g_qp);
    cudaGetSymbolAddress((void**)&kp, g_kp);
    cudaGetSymbolAddress((void**)&vp, g_vp);
    cudaGetSymbolAddress((void**)&vth, g_vth);
    cudaGetSymbolAddress((void**)&vals, g_vals);
    cudaGetSymbolAddress((void**)&x, g_x);
    cudaGetSymbolAddress((void**)&ln, g_ln);
    cudaGetSymbolAddress((void**)&ff, g_ff);

    const int S_128_128 = 2 * (128 + 128) * 36 * 4;        // 73728
    const int S_QK  = 2 * 128 * 68 * 4;                    // 69632
    const int S_AV  = 4*64*AVLD*2 + 64*4;                  // 37120
    cudaFuncSetAttribute(gemm_tf32<0,128,128,2,4>, cudaFuncAttributeMaxDynamicSharedMemorySize, S_128_128);
    cudaFuncSetAttribute(gemm_tf32<1,128,128,2,4>, cudaFuncAttributeMaxDynamicSharedMemorySize, S_128_128);
    cudaFuncSetAttribute(gemm_tf32<2,128,128,2,4>, cudaFuncAttributeMaxDynamicSharedMemorySize, S_128_128);
    cudaFuncSetAttribute(qk_rope_exp_kernel, cudaFuncAttributeMaxDynamicSharedMemorySize, S_QK);
    cudaFuncSetAttribute(av_half_kernel, cudaFuncAttributeMaxDynamicSharedMemorySize, S_AV);

    rope_table_kernel<<<(SEQ*32 + 255)/256, 256>>>();

    // QKV projections
    gemm_tf32<0,128,128,2,4><<<dim3(EMB/128, ROWS/128, 1), 256, S_128_128>>>(
        plm, Wq, bq, nullptr, qp, PLMD, PLMD, PLMD, EMB);
    gemm_tf32<0,128,128,2,4><<<dim3(EMB/128, ROWS/128, 1), 256, S_128_128>>>(
        s_repre, Wk, bk, nullptr, kp, SD, SD, SD, EMB);
    gemm_tf32<0,128,128,2,4><<<dim3(EMB/128, ROWS/128, 1), 256, S_128_128>>>(
        s_repre, Wv, bv, nullptr, vp, SD, SD, SD, EMB);

    // V transpose to [BH,D,S] fp16
    v_transpose_kernel<<<dim3(SEQ/32, HD/32, BH), 256>>>(vp, vth);

    // exp(QK^T/8) with fused RoPE -> g_eh (fp16, coalesced) + partial sums
    qk_rope_exp_kernel<<<dim3(SEQ/128, SEQ/128, BH), 256, S_QK>>>(qp, kp);

    // finalize 1/rowsum
    reduce_stats_kernel<<<(BH*SEQ + 255)/256, 256>>>();

    // AV on fp16 E/V: probs (fp32, once) -> d_out, O*rinv -> merged vals
    av_half_kernel<<<dim3(1, SEQ/64, BH), 256, S_AV>>>(attn, vals);

    // o = vals @ Wo^T + bo + plm (residual fused)
    gemm_tf32<1,128,128,2,4><<<dim3(PLMD/128, ROWS/128, 1), 256, S_128_128>>>(
        vals, Wo, bo, plm, x, EMB, EMB, EMB, PLMD);

    layernorm_kernel<<<ROWS, 256>>>(x, lng, lnb, ln);

    gemm_tf32<2,128,128,2,4><<<dim3(FFD/128, ROWS/128, 1), 256, S_128_128>>>(
        ln, Wd, bd, nullptr, ff, PLMD, PLMD, PLMD, FFD);

    gemm_tf32<1,128,128,2,4><<<dim3(PLMD/128, ROWS/128, 1), 256, S_128_128>>>(
        ff, Wu, bu, ln, out, FFD, FFD, FFD, PLMD);
}

// round 16
// speedup vs baseline: 1.1854x; 1.1854x over previous
#include <cuda_runtime.h>
#include <cuda_fp16.h>
#include <math.h>
#include <stdint.h>

#define BATCH 2
#define SEQ   2048
#define NH    12
#define HD    64
#define EMB   768     // NH*HD
#define PLMD  1280
#define SD    128
#define FFD   640
#define ROWS  (BATCH*SEQ)                 // 4096
#define BH    (BATCH*NH)                  // 24
#define OUT_ELEMS ((long)ROWS*PLMD)       // 5,242,880
#define LOG2_10000 13.287712379549449f

// ---------------- scratch (static __device__, no allocation) ----------------
__device__ __align__(16) float g_qp[ROWS*EMB];
__device__ __align__(16) float g_kp[ROWS*EMB];
__device__ __align__(16) float g_vp[ROWS*EMB];
__device__ __align__(16) float g_vals[ROWS*EMB]; // [B,S,E]
__device__ __align__(16) float g_x[ROWS*PLMD];
__device__ __align__(16) float g_ln[ROWS*PLMD];
__device__ __align__(16) float g_ff[ROWS*FFD];
__device__ __align__(16) float g_cos[SEQ*32];
__device__ __align__(16) float g_sin[SEQ*32];
__device__ __align__(16) float g_psum[BH*16*SEQ];  // [bh][colblk][row]
__device__ __align__(16) float g_rinv[BH*SEQ];
__device__ __align__(16) __half g_qh[ROWS*EMB];    // [BH,S,D] roped*0.125 fp16
__device__ __align__(16) __half g_kh[ROWS*EMB];    // [BH,S,D] roped fp16
__device__ __align__(16) __half g_eh[100663296];   // BH*SEQ*SEQ fp16 exp values
__device__ __align__(16) __half g_vth[ROWS*EMB];   // [BH,D,S] fp16 V^T

// ---------------- helpers ----------------
__device__ __forceinline__ uint32_t f2tf32(uint32_t xbits) {
    uint32_t u;
    float f = __uint_as_float(xbits);
    asm("cvt.rna.tf32.f32 %0, %1;" : "=r"(u) : "f"(f));
    return u;
}

__device__ __forceinline__ void mma_tf32(float* c, const uint32_t* a, const uint32_t* b) {
    asm volatile("mma.sync.aligned.m16n8k8.row.col.f32.tf32.tf32.f32 "
        "{%0,%1,%2,%3}, {%4,%5,%6,%7}, {%8,%9}, {%0,%1,%2,%3};"
        : "+f"(c[0]), "+f"(c[1]), "+f"(c[2]), "+f"(c[3])
        : "r"(a[0]), "r"(a[1]), "r"(a[2]), "r"(a[3]), "r"(b[0]), "r"(b[1]));
}

__device__ __forceinline__ void mma_f16(float* c, const uint32_t* a, const uint32_t* b) {
    asm volatile("mma.sync.aligned.m16n8k16.row.col.f32.f16.f16.f32 "
        "{%0,%1,%2,%3}, {%4,%5,%6,%7}, {%8,%9}, {%0,%1,%2,%3};"
        : "+f"(c[0]), "+f"(c[1]), "+f"(c[2]), "+f"(c[3])
        : "r"(a[0]), "r"(a[1]), "r"(a[2]), "r"(a[3]), "r"(b[0]), "r"(b[1]));
}

__device__ __forceinline__ void cp_async16(uint32_t smem_dst, const void* gsrc) {
    asm volatile("cp.async.cg.shared.global [%0], [%1], 16;" :: "r"(smem_dst), "l"(gsrc));
}
__device__ __forceinline__ void cp_commit() { asm volatile("cp.async.commit_group;"); }
__device__ __forceinline__ void cp_wait1()  { asm volatile("cp.async.wait_group 1;"); }

// ---------------- RoPE cos/sin tables ----------------
__global__ void rope_table_kernel() {
    int idx = blockIdx.x * blockDim.x + threadIdx.x;
    if (idx >= SEQ*32) return;
    int s = idx >> 5, j = idx & 31;
    float inv = exp2f(-(float)j * (LOG2_10000 / 32.0f));
    float freq = (float)s * inv;
    float sn, c;
    sincosf(freq, &sn, &c);
    g_cos[idx] = c; g_sin[idx] = sn;
}

// ---------------- rope apply: [B,S,H*D] -> [BH,S,D] fp16 (optionally *0.125)
template<bool SCALE>
__global__ void rope_apply_kernel(const float* __restrict__ src, __half* __restrict__ dst)
{
    int idx = blockIdx.x * blockDim.x + threadIdx.x;
    if (idx >= ROWS*EMB) return;
    int d = idx & 63;
    int s = (idx >> 6) & (SEQ-1);
    int t = idx >> 17;
    int h = t % NH;
    int b = t / NH;
    long srcoff = (long)(b*SEQ + s)*EMB + h*HD + d;
    int j = d & 31;
    float c  = g_cos[s*32 + j];
    float sn = g_sin[s*32 + j];
    float x = src[srcoff];
    float pr = (d < 32) ? -src[srcoff + 32] : src[srcoff - 32];
    float val = x*c + pr*sn;
    if (SCALE) val *= 0.125f;
    dst[((long)(b*NH + h)*SEQ + s)*HD + d] = __float2half_rn(val);
}

// ---------------- V transpose (tiled): [B,S,H*D] -> [BH,D,S] fp16 -----------
__global__ __launch_bounds__(256)
void v_transpose_kernel(const float* __restrict__ src, __half* __restrict__ dst)
{
    __shared__ float t[32][33];
    const int bh = blockIdx.z;
    const int b = bh / NH, h = bh % NH;
    const int d0 = blockIdx.y * 32;
    const int s0 = blockIdx.x * 32;
    const int col = threadIdx.x & 31;
    const int rw  = threadIdx.x >> 5;
#pragma unroll
    for (int i = 0; i < 4; i++) {
        int row = rw + i*8;
        t[row][col] = src[(long)(b*SEQ + s0 + row)*EMB + h*HD + d0 + col];
    }
    __syncthreads();
#pragma unroll
    for (int i = 0; i < 4; i++) {
        int d = rw + i*8;
        dst[((long)bh*HD + d0 + d)*SEQ + s0 + col] = __float2half_rn(t[col][d]);
    }
}

// ---------------- TF32 pipelined GEMM: C = A@B^T (+bias)(+extra)(gelu) ----
template<int EPI, int BM, int BN, int WARPS_M, int WARPS_N>
__global__ __launch_bounds__(256)
void gemm_tf32(const float* __restrict__ A, const float* __restrict__ B,
               const float* __restrict__ bias, const float* __restrict__ extra,
               float* __restrict__ C,
               int K, int sAm, int sBn, int ldc)
{
    constexpr int BK   = 32;
    constexpr int LDSW = 36;
    constexpr int WM = BM / WARPS_M, WN = BN / WARPS_N;
    constexpr int MF = WM / 16, NF = WN / 8;
    constexpr int ASTG = BM * LDSW;
    constexpr int BSTG = BN * LDSW;

    extern __shared__ uint32_t smem[];
    uint32_t* As = smem;
    uint32_t* Bs = smem + 2 * ASTG;

    const int tid  = threadIdx.x;
    const int lane = tid & 31;
    const int warp = tid >> 5;
    const int wm = warp % WARPS_M, wn = warp / WARPS_M;
    const int row0 = blockIdx.y * BM, col0 = blockIdx.x * BN;
    A += (long)row0 * sAm;
    B += (long)col0 * sBn;

    const uint32_t smem_base = (uint32_t)__cvta_generic_to_shared(smem);
    const int r  = lane >> 2;
    const int cq = lane & 3;

    float acc[MF][NF][4];
#pragma unroll
    for (int m = 0; m < MF; m++)
#pragma unroll
        for (int n = 0; n < NF; n++)
#pragma unroll
            for (int j = 0; j < 4; j++) acc[m][n][j] = 0.f;

    const int lrow = tid >> 3;
    const int lf   = (tid & 7) * 4;

    auto prefetch = [&](int stage, int k0) {
#pragma unroll
        for (int i = 0; i < BM/32; i++) {
            int row = lrow + i*32;
            cp_async16(smem_base + (stage*ASTG + row*LDSW + lf)*4,
                       A + (long)row*sAm + k0 + lf);
        }
#pragma unroll
        for (int i = 0; i < BN/32; i++) {
            int row = lrow + i*32;
            cp_async16(smem_base + ((2*ASTG) + stage*BSTG + row*LDSW + lf)*4,
                       B + (long)row*sBn + k0 + lf);
        }
    };

    const int nk = K / BK;
    prefetch(0, 0);
    cp_commit();

    for (int kt = 0; kt < nk; kt++) {
        const int stage = kt & 1;
        if (kt + 1 < nk) prefetch(stage ^ 1, (kt+1) * BK);
        cp_commit();
        cp_wait1();
        __syncthreads();

        const uint32_t* Ast = As + stage * ASTG;
        const uint32_t* Bst = Bs + stage * BSTG;
#pragma unroll
        for (int ks = 0; ks < BK/8; ks++) {
            const int kk = ks * 8;
            uint32_t af[MF][4], bf[NF][2];
#pragma unroll
            for (int m = 0; m < MF; m++) {
                int base = (wm*WM + m*16 + r)*LDSW + kk + cq;
                af[m][0] = f2tf32(Ast[base]);
                af[m][1] = f2tf32(Ast[base + 8*LDSW]);
                af[m][2] = f2tf32(Ast[base + 4]);
                af[m][3] = f2tf32(Ast[base + 8*LDSW + 4]);
            }
#pragma unroll
            for (int n = 0; n < NF; n++) {
                int base = (wn*WN + n*8 + r)*LDSW + kk + cq;
                bf[n][0] = f2tf32(Bst[base]);
                bf[n][1] = f2tf32(Bst[base + 4]);
            }
#pragma unroll
            for (int m = 0; m < MF; m++)
#pragma unroll
                for (int n = 0; n < NF; n++)
                    mma_tf32(acc[m][n], af[m], bf[n]);
        }
        __syncthreads();
    }

#pragma unroll
    for (int m = 0; m < MF; m++) {
#pragma unroll
        for (int n = 0; n < NF; n++) {
            int row = row0 + wm*WM + m*16 + r;
            int col = col0 + wn*WN + n*8 + 2*cq;
            float v0 = acc[m][n][0];
            float v1 = acc[m][n][1];
            float v2 = acc[m][n][2];
            float v3 = acc[m][n][3];
            if (bias) { v0 += bias[col]; v1 += bias[col+1]; v2 += bias[col]; v3 += bias[col+1]; }
            if (EPI == 1) {
                v0 += extra[(long)row*ldc + col];
                v1 += extra[(long)row*ldc + col + 1];
                v2 += extra[(long)(row+8)*ldc + col];
                v3 += extra[(long)(row+8)*ldc + col + 1];
            }
            if (EPI == 2) {
                v0 = 0.5f * v0 * (1.f + erff(v0 * 0.70710678118654752f));
                v1 = 0.5f * v1 * (1.f + erff(v1 * 0.70710678118654752f));
                v2 = 0.5f * v2 * (1.f + erff(v2 * 0.70710678118654752f));
                v3 = 0.5f * v3 * (1.f + erff(v3 * 0.70710678118654752f));
            }
            *reinterpret_cast<float2*>(&C[(long)row*ldc + col])     = make_float2(v0, v1);
            *reinterpret_cast<float2*>(&C[(long)(row+8)*ldc + col]) = make_float2(v2, v3);
        }
    }
}

// ---------------- QK^T (fp16 MMA): E = exp(s/8) fp16 (coalesced) + sums -----
#define LDQ 72      // halfs per Q/K SMEM row
#define LDE 136     // halfs per Eh row
__global__ __launch_bounds__(256)
void qk_exp_kernel(const __half* __restrict__ qh, const __half* __restrict__ kh)
{
    extern __shared__ float sm[];
    __half* Qs = reinterpret_cast<__half*>(sm);     // [128*LDQ]
    __half* Ks = Qs + 128*LDQ;

    const int tid  = threadIdx.x;
    const int lane = tid & 31;
    const int warp = tid >> 5;
    const int wm = warp & 1, wn = warp >> 1;   // 2 x 4 warps: warp tile 64x32
    const int bh = blockIdx.z;
    const int row0 = blockIdx.y * 128, col0 = blockIdx.x * 128;
    const int r  = lane >> 2;
    const int cq = lane & 3;

    const __half* qb = qh + ((long)bh*SEQ + row0)*HD;
    const __half* kb = kh + ((long)bh*SEQ + col0)*HD;

    const uint32_t q_base = (uint32_t)__cvta_generic_to_shared(Qs);
    const uint32_t k_base = (uint32_t)__cvta_generic_to_shared(Ks);

    // stage: 128 rows x 64 halves = 8 x 16B chunks per row, per tile
#pragma unroll
    for (int i = 0; i < 4; i++) {
        int idx = tid + i*256;
        int row = idx >> 3, ch = (idx & 7) * 8;
        cp_async16(q_base + (row*LDQ + ch)*2, qb + (long)row*HD + ch);
        cp_async16(k_base + (row*LDQ + ch)*2, kb + (long)row*HD + ch);
    }
    cp_commit();
    asm volatile("cp.async.wait_group 0;");
    __syncthreads();

    float acc[4][4][4];
#pragma unroll
    for (int m = 0; m < 4; m++)
#pragma unroll
        for (int n = 0; n < 4; n++)
#pragma unroll
            for (int j = 0; j < 4; j++) acc[m][n][j] = 0.f;

#pragma unroll
    for (int ks = 0; ks < 4; ks++) {       // K=64 in 4 k16 steps
        const int kk = ks * 16;
        uint32_t af[4][4], bf[4][2];
#pragma unroll
        for (int m = 0; m < 4; m++) {
            int rowa = wm*64 + m*16 + r;
            af[m][0] = *reinterpret_cast<const uint32_t*>(&Qs[rowa*LDQ + kk + 2*cq]);
            af[m][1] = *reinterpret_cast<const uint32_t*>(&Qs[(rowa+8)*LDQ + kk + 2*cq]);
            af[m][2] = *reinterpret_cast<const uint32_t*>(&Qs[rowa*LDQ + kk + 2*cq + 8]);
            af[m][3] = *reinterpret_cast<const uint32_t*>(&Qs[(rowa+8)*LDQ + kk + 2*cq + 8]);
        }
#pragma unroll
        for (int n = 0; n < 4; n++) {
            int rowb = wn*32 + n*8 + r;
            bf[n][0] = *reinterpret_cast<const uint32_t*>(&Ks[rowb*LDQ + kk + 2*cq]);
            bf[n][1] = *reinterpret_cast<const uint32_t*>(&Ks[rowb*LDQ + kk + 2*cq + 8]);
        }
#pragma unroll
        for (int m = 0; m < 4; m++)
#pragma unroll
            for (int n = 0; n < 4; n++)
                mma_f16(acc[m][n], af[m], bf[n]);
    }

    // exp — the only exp pass in the whole pipeline (q pre-scaled by 1/8)
#pragma unroll
    for (int m = 0; m < 4; m++)
#pragma unroll
        for (int n = 0; n < 4; n++)
#pragma unroll
            for (int j = 0; j < 4; j++)
                acc[m][n][j] = __expf(acc[m][n][j]);

    // ---- stage E into SMEM (fp16) + partial sums ----
    __syncthreads();              // Qs/Ks dead; reuse as Eh + Sred
    __half* Eh = reinterpret_cast<__half*>(sm);         // [128][LDE]
    float* Sred = sm + (128*LDE)/2;                     // [128][17]
    const int slot = wn*4 + cq;

#pragma unroll
    for (int m = 0; m < 4; m++) {
#pragma unroll
        for (int n = 0; n < 4; n++) {
            int row = wm*64 + m*16 + r;
            int col = wn*32 + n*8 + 2*cq;
            *reinterpret_cast<__half2*>(&Eh[row*LDE + col]) =
                __floats2half2_rn(acc[m][n][0], acc[m][n][1]);
            *reinterpret_cast<__half2*>(&Eh[(row+8)*LDE + col]) =
                __floats2half2_rn(acc[m][n][2], acc[m][n][3]);
        }
    }
#pragma unroll
    for (int m = 0; m < 4; m++)
#pragma unroll
        for (int hf = 0; hf < 2; hf++) {
            int rl = wm*64 + m*16 + r + hf*8;
            float s = 0.f;
#pragma unroll
            for (int n = 0; n < 4; n++)
                s += acc[m][n][hf*2] + acc[m][n][hf*2+1];
            Sred[rl*17 + slot] = s;
        }
    __syncthreads();

    // ---- coalesced fp16 store: 2 threads per row ----
    __half* Eb = g_eh + (long)bh*SEQ*SEQ;
    {
        int row = tid >> 1;
        long gbase = (long)(row0 + row)*SEQ + col0;
#pragma unroll
        for (int j = 0; j < 8; j++) {
            int ho = ((tid & 1) + 2*j) * 8;
            uint4 v = *reinterpret_cast<const uint4*>(&Eh[row*LDE + ho]);
            __stcs(reinterpret_cast<uint4*>(Eb + gbase + ho), v);
        }
    }
    if (tid < 128) {
        float s = 0.f;
#pragma unroll
        for (int i = 0; i < 16; i++) s += Sred[tid*17 + i];
        g_psum[(long)(bh*16 + blockIdx.x)*SEQ + row0 + tid] = s;
    }
}

// ---------------- reduce 16 partials per row -> 1/sum ----------------
__global__ __launch_bounds__(256)
void reduce_stats_kernel()
{
    int rg = blockIdx.x * 256 + threadIdx.x;
    if (rg >= BH*SEQ) return;
    int bh = rg >> 11, row = rg & (SEQ-1);
    long base = (long)bh*16*SEQ + row;
    float s = 0.f;
#pragma unroll
    for (int i = 0; i < 16; i++) s += g_psum[base + (long)i*SEQ];
    g_rinv[rg] = 1.f / s;
}

// ---------------- AV (fp16 MMA on E, V^T): probs (fp32) + merged O ----------
#define AVLD 72   // halfs per SMEM row (64 + 8 pad)
__global__ __launch_bounds__(256)
void av_half_kernel(float* __restrict__ attn, float* __restrict__ vals)
{
    extern __shared__ float smf[];
    __half* Ah = reinterpret_cast<__half*>(smf);          // [2][64*AVLD]
    __half* Bh = Ah + 2*64*AVLD;                          // [2][64*AVLD]
    float*  rinv_s = smf + (4*64*AVLD)/2;                 // [64]

    const int tid  = threadIdx.x;
    const int lane = tid & 31;
    const int warp = tid >> 5;
    const int wm = warp & 1, wn = warp >> 1;   // 2 x 4 -> warp tile 32x16
    const int bh = blockIdx.z;
    const int b = bh / NH, h = bh % NH;
    const int row0 = blockIdx.y * 64;
    const int r  = lane >> 2;
    const int cq = lane & 3;

    const __half* Eb = g_eh + (long)bh*SEQ*SEQ + (long)row0*SEQ;
    const __half* Vb = g_vth + (long)bh*HD*SEQ;
    float* Ab = attn + (long)bh*SEQ*SEQ + (long)row0*SEQ;

    if (tid < 64) rinv_s[tid] = g_rinv[bh*SEQ + row0 + tid];

    const uint32_t a_base = (uint32_t)__cvta_generic_to_shared(Ah);
    const uint32_t b_base = (uint32_t)__cvta_generic_to_shared(Bh);

    auto prefetch = [&](int stage, int k0) {
#pragma unroll
        for (int i = 0; i < 2; i++) {
            int idx = tid + i*256;
            int row = idx >> 3, ch = (idx & 7) * 8;
            cp_async16(a_base + (stage*64*AVLD + row*AVLD + ch)*2,
                       Eb + (long)row*SEQ + k0 + ch);
            cp_async16(b_base + (stage*64*AVLD + row*AVLD + ch)*2,
                       Vb + (long)row*SEQ + k0 + ch);
        }
    };

    float acc[2][2][4];
#pragma unroll
    for (int m = 0; m < 2; m++)
#pragma unroll
        for (int n = 0; n < 2; n++)
#pragma unroll
            for (int j = 0; j < 4; j++) acc[m][n][j] = 0.f;

    prefetch(0, 0);
    cp_commit();

    for (int kt = 0; kt < 32; kt++) {
        const int stage = kt & 1;
        if (kt + 1 < 32) prefetch(stage ^ 1, (kt+1) * 64);
        cp_commit();
        cp_wait1();
        __syncthreads();

        const __half* Ast = Ah + stage*64*AVLD;
        const __half* Bst = Bh + stage*64*AVLD;

        // ---- coalesced prob store: 16 threads/row x float4 = 256B runs ----
#pragma unroll
        for (int g = 0; g < 4; g++) {
            int row  = g*16 + (tid >> 4);
            int colf = (tid & 15) * 4;
            __half2 h01 = *reinterpret_cast<const __half2*>(&Ast[row*AVLD + colf]);
            __half2 h23 = *reinterpret_cast<const __half2*>(&Ast[row*AVLD + colf + 2]);
            float riv = rinv_s[row];
            float4 o;
            o.x = __low2float(h01)  * riv;
            o.y = __high2float(h01) * riv;
            o.z = __low2float(h23)  * riv;
            o.w = __high2float(h23) * riv;
            __stcs(reinterpret_cast<float4*>(Ab + (long)row*SEQ + kt*64 + colf), o);
        }

        // ---- fp16 MMA on raw E / raw V (no conversions) ----
#pragma unroll
        for (int ks = 0; ks < 4; ks++) {
            const int kk = ks * 16;
            uint32_t af[2][4], bf[2][2];
#pragma unroll
            for (int m = 0; m < 2; m++) {
                int rowa = wm*32 + m*16 + r;
                af[m][0] = *reinterpret_cast<const uint32_t*>(&Ast[rowa*AVLD + kk + 2*cq]);
                af[m][1] = *reinterpret_cast<const uint32_t*>(&Ast[(rowa+8)*AVLD + kk + 2*cq]);
                af[m][2] = *reinterpret_cast<const uint32_t*>(&Ast[rowa*AVLD + kk + 2*cq + 8]);
                af[m][3] = *reinterpret_cast<const uint32_t*>(&Ast[(rowa+8)*AVLD + kk + 2*cq + 8]);
            }
#pragma unroll
            for (int n = 0; n < 2; n++) {
                int rowb = wn*16 + n*8 + r;
                bf[n][0] = *reinterpret_cast<const uint32_t*>(&Bst[rowb*AVLD + kk + 2*cq]);
                bf[n][1] = *reinterpret_cast<const uint32_t*>(&Bst[rowb*AVLD + kk + 2*cq + 8]);
            }
#pragma unroll
            for (int m = 0; m < 2; m++)
#pragma unroll
                for (int n = 0; n < 2; n++)
                    mma_f16(acc[m][n], af[m], bf[n]);
        }
        __syncthreads();
    }

    // epilogue: scale O rows by rinv, write merged [B,S,H*D]
#pragma unroll
    for (int m = 0; m < 2; m++) {
        int lr = wm*32 + m*16 + r;
        float s0 = rinv_s[lr], s1 = rinv_s[lr + 8];
#pragma unroll
        for (int n = 0; n < 2; n++) {
            int srow = row0 + lr;
            int col  = h*HD + wn*16 + n*8 + 2*cq;
            *reinterpret_cast<float2*>(&vals[(long)(b*SEQ + srow)*EMB + col]) =
                make_float2(acc[m][n][0]*s0, acc[m][n][1]*s0);
            *reinterpret_cast<float2*>(&vals[(long)(b*SEQ + srow + 8)*EMB + col]) =
                make_float2(acc[m][n][2]*s1, acc[m][n][3]*s1);
        }
    }
}

// ---------------- LayerNorm over 1280 ----------------
__global__ __launch_bounds__(256) void layernorm_kernel(const float* __restrict__ x,
    const float* __restrict__ g, const float* __restrict__ b, float* __restrict__ y)
{
    __shared__ float buf[PLMD];
    __shared__ float red[256];
    long row = blockIdx.x;
    const float* xr = x + row*PLMD;
    int tid = threadIdx.x;
    float s = 0.f;
    for (int i = tid; i < PLMD; i += 256) { float t = xr[i]; buf[i] = t; s += t; }
    red[tid] = s; __syncthreads();
    for (int st = 128; st > 0; st >>= 1) { if (tid < st) red[tid] += red[tid+st]; __syncthreads(); }
    float mu = red[0] * (1.f/PLMD); __syncthreads();
    float vs = 0.f;
    for (int i = tid; i < PLMD; i += 256) { float d = buf[i] - mu; vs += d*d; }
    red[tid] = vs; __syncthreads();
    for (int st = 128; st > 0; st >>= 1) { if (tid < st) red[tid] += red[tid+st]; __syncthreads(); }
    float rstd = rsqrtf(red[0] * (1.f/PLMD) + 1e-5f);
    float* yr = y + row*PLMD;
    for (int i = tid; i < PLMD; i += 256) yr[i] = (buf[i] - mu) * rstd * g[i] + b[i];
}

// ---------------- launch ----------------
extern "C" void kernel_launch(void* const* d_in, const int* in_sizes, int n_in,
                              void* d_out, int out_size)
{
    const float* s_repre = (const float*)d_in[0];
    const float* plm     = (const float*)d_in[1];
    const float* Wq = (const float*)d_in[2];  const float* bq = (const float*)d_in[3];
    const float* Wk = (const float*)d_in[4];  const float* bk = (const float*)d_in[5];
    const float* Wv = (const float*)d_in[6];  const float* bv = (const float*)d_in[7];
    const float* Wo = (const float*)d_in[8];  const float* bo = (const float*)d_in[9];
    const float* lng = (const float*)d_in[10]; const float* lnb = (const float*)d_in[11];
    const float* Wd = (const float*)d_in[12]; const float* bd = (const float*)d_in[13];
    const float* Wu = (const float*)d_in[14]; const float* bu = (const float*)d_in[15];

    float* out  = (float*)d_out;
    float* attn = out + OUT_ELEMS;   // tuple order: (out, attention)

    float *qp,*kp,*vp,*vals,*x,*ln,*ff;
    __half *qh,*kh,*vth;
    cudaGetSymbolAddress((void**)&qp, g_qp);
    cudaGetSymbolAddress((void**)&kp, g_kp);
    cudaGetSymbolAddress((void**)&vp, g_vp);
    cudaGetSymbolAddress((void**)&qh, g_qh);
    cudaGetSymbolAddress((void**)&kh, g_kh);
    cudaGetSymbolAddress((void**)&vth, g_vth);
    cudaGetSymbolAddress((void**)&vals, g_vals);
    cudaGetSymbolAddress((void**)&x, g_x);
    cudaGetSymbolAddress((void**)&ln, g_ln);
    cudaGetSymbolAddress((void**)&ff, g_ff);

    const int S_128_128 = 2 * (128 + 128) * 36 * 4;        // 73728
    const int S_QK  = 128*LDE*2 + 128*17*4;                // 43520 (>= staging 36864)
    const int S_AV  = 4*64*AVLD*2 + 64*4;                  // 37120
    cudaFuncSetAttribute(gemm_tf32<0,128,128,2,4>, cudaFuncAttributeMaxDynamicSharedMemorySize, S_128_128);
    cudaFuncSetAttribute(gemm_tf32<1,128,128,2,4>, cudaFuncAttributeMaxDynamicSharedMemorySize, S_128_128);
    cudaFuncSetAttribute(gemm_tf32<2,128,128,2,4>, cudaFuncAttributeMaxDynamicSharedMemorySize, S_128_128);
    cudaFuncSetAttribute(qk_exp_kernel, cudaFuncAttributeMaxDynamicSharedMemorySize, S_QK);
    cudaFuncSetAttribute(av_half_kernel, cudaFuncAttributeMaxDynamicSharedMemorySize, S_AV);

    const int tot = ROWS*EMB;

    rope_table_kernel<<<(SEQ*32 + 255)/256, 256>>>();

    // QKV projections
    gemm_tf32<0,128,128,2,4><<<dim3(EMB/128, ROWS/128, 1), 256, S_128_128>>>(
        plm, Wq, bq, nullptr, qp, PLMD, PLMD, PLMD, EMB);
    gemm_tf32<0,128,128,2,4><<<dim3(EMB/128, ROWS/128, 1), 256, S_128_128>>>(
        s_repre, Wk, bk, nullptr, kp, SD, SD, SD, EMB);
    gemm_tf32<0,128,128,2,4><<<dim3(EMB/128, ROWS/128, 1), 256, S_128_128>>>(
        s_repre, Wv, bv, nullptr, vp, SD, SD, SD, EMB);

    // rope -> fp16 [BH,S,D] (q pre-scaled), V transpose -> fp16 [BH,D,S]
    rope_apply_kernel<true ><<<(tot+255)/256, 256>>>(qp, qh);
    rope_apply_kernel<false><<<(tot+255)/256, 256>>>(kp, kh);
    v_transpose_kernel<<<dim3(SEQ/32, HD/32, BH), 256>>>(vp, vth);

    // exp(QK^T/8) fp16 MMA -> g_eh (fp16, coalesced) + partial sums
    qk_exp_kernel<<<dim3(SEQ/128, SEQ/128, BH), 256, S_QK>>>(qh, kh);

    // finalize 1/rowsum
    reduce_stats_kernel<<<(BH*SEQ + 255)/256, 256>>>();

    // AV fp16 MMA: probs (fp32, once) -> d_out, O*rinv -> merged vals
    av_half_kernel<<<dim3(1, SEQ/64, BH), 256, S_AV>>>(attn, vals);

    // o = vals @ Wo^T + bo + plm (residual fused)
    gemm_tf32<1,128,128,2,4><<<dim3(PLMD/128, ROWS/128, 1), 256, S_128_128>>>(
        vals, Wo, bo, plm, x, EMB, EMB, EMB, PLMD);

    layernorm_kernel<<<ROWS, 256>>>(x, lng, lnb, ln);

    gemm_tf32<2,128,128,2,4><<<dim3(FFD/128, ROWS/128, 1), 256, S_128_128>>>(
        ln, Wd, bd, nullptr, ff, PLMD, PLMD, PLMD, FFD);

    gemm_tf32<1,128,128,2,4><<<dim3(PLMD/128, ROWS/128, 1), 256, S_128_128>>>(
        ff, Wu, bu, ln, out, FFD, FFD, FFD, PLMD);
}

// round 17
// speedup vs baseline: 1.2063x; 1.0176x over previous
#include <cuda_runtime.h>
#include <cuda_fp16.h>
#include <math.h>
#include <stdint.h>

#define BATCH 2
#define SEQ   2048
#define NH    12
#define HD    64
#define EMB   768     // NH*HD
#define PLMD  1280
#define SD    128
#define FFD   640
#define ROWS  (BATCH*SEQ)                 // 4096
#define BH    (BATCH*NH)                  // 24
#define OUT_ELEMS ((long)ROWS*PLMD)       // 5,242,880
#define LOG2_10000 13.287712379549449f

// ---------------- scratch (static __device__, no allocation) ----------------
__device__ __align__(16) float g_qp[ROWS*EMB];
__device__ __align__(16) float g_kp[ROWS*EMB];
__device__ __align__(16) float g_vp[ROWS*EMB];
__device__ __align__(16) float g_vals[ROWS*EMB]; // [B,S,E]
__device__ __align__(16) float g_x[ROWS*PLMD];
__device__ __align__(16) float g_ln[ROWS*PLMD];
__device__ __align__(16) float g_ff[ROWS*FFD];
__device__ __align__(16) float g_cos[SEQ*32];
__device__ __align__(16) float g_sin[SEQ*32];
__device__ __align__(16) float g_psum[BH*16*SEQ];  // [bh][colblk][row]
__device__ __align__(16) float g_rinv[BH*SEQ];
__device__ __align__(16) __half g_qh[ROWS*EMB];    // [BH,S,D] roped*0.125 fp16
__device__ __align__(16) __half g_kh[ROWS*EMB];    // [BH,S,D] roped fp16
__device__ __align__(16) __half g_eh[100663296];   // BH*SEQ*SEQ fp16 exp values
__device__ __align__(16) __half g_vth[ROWS*EMB];   // [BH,D,S] fp16 V^T

// ---------------- helpers ----------------
__device__ __forceinline__ uint32_t f2tf32(uint32_t xbits) {
    uint32_t u;
    float f = __uint_as_float(xbits);
    asm("cvt.rna.tf32.f32 %0, %1;" : "=r"(u) : "f"(f));
    return u;
}

__device__ __forceinline__ void mma_tf32(float* c, const uint32_t* a, const uint32_t* b) {
    asm volatile("mma.sync.aligned.m16n8k8.row.col.f32.tf32.tf32.f32 "
        "{%0,%1,%2,%3}, {%4,%5,%6,%7}, {%8,%9}, {%0,%1,%2,%3};"
        : "+f"(c[0]), "+f"(c[1]), "+f"(c[2]), "+f"(c[3])
        : "r"(a[0]), "r"(a[1]), "r"(a[2]), "r"(a[3]), "r"(b[0]), "r"(b[1]));
}

__device__ __forceinline__ void mma_f16(float* c, const uint32_t* a, const uint32_t* b) {
    asm volatile("mma.sync.aligned.m16n8k16.row.col.f32.f16.f16.f32 "
        "{%0,%1,%2,%3}, {%4,%5,%6,%7}, {%8,%9}, {%0,%1,%2,%3};"
        : "+f"(c[0]), "+f"(c[1]), "+f"(c[2]), "+f"(c[3])
        : "r"(a[0]), "r"(a[1]), "r"(a[2]), "r"(a[3]), "r"(b[0]), "r"(b[1]));
}

__device__ __forceinline__ void cp_async16(uint32_t smem_dst, const void* gsrc) {
    asm volatile("cp.async.cg.shared.global [%0], [%1], 16;" :: "r"(smem_dst), "l"(gsrc));
}
__device__ __forceinline__ void cp_commit() { asm volatile("cp.async.commit_group;"); }
__device__ __forceinline__ void cp_wait1()  { asm volatile("cp.async.wait_group 1;"); }
__device__ __forceinline__ void cp_wait0()  { asm volatile("cp.async.wait_group 0;"); }

// ---------------- RoPE cos/sin tables ----------------
__global__ void rope_table_kernel() {
    int idx = blockIdx.x * blockDim.x + threadIdx.x;
    if (idx >= SEQ*32) return;
    int s = idx >> 5, j = idx & 31;
    float inv = exp2f(-(float)j * (LOG2_10000 / 32.0f));
    float freq = (float)s * inv;
    float sn, c;
    sincosf(freq, &sn, &c);
    g_cos[idx] = c; g_sin[idx] = sn;
}

// ---------------- rope apply (vectorized): [B,S,H*D] -> [BH,S,D] fp16 -------
template<bool SCALE>
__global__ void rope_apply_kernel(const float* __restrict__ src, __half* __restrict__ dst)
{
    int idx = blockIdx.x * blockDim.x + threadIdx.x;   // one per 4 elems
    if (idx >= ROWS*EMB/4) return;
    int d0 = (idx & 15) * 4;               // 0,4,...,60
    int s  = (idx >> 4) & (SEQ-1);
    int t  = idx >> 15;
    int h  = t % NH;
    int b  = t / NH;
    long base = (long)(b*SEQ + s)*EMB + h*HD;
    int j0 = d0 & 31;
    float sgn = (d0 < 32) ? -1.f : 1.f;
    float4 x  = *reinterpret_cast<const float4*>(src + base + d0);
    float4 p  = *reinterpret_cast<const float4*>(src + base + (d0 ^ 32));
    float4 c  = *reinterpret_cast<const float4*>(&g_cos[s*32 + j0]);
    float4 sn = *reinterpret_cast<const float4*>(&g_sin[s*32 + j0]);
    float4 o;
    o.x = x.x*c.x + sgn*p.x*sn.x;
    o.y = x.y*c.y + sgn*p.y*sn.y;
    o.z = x.z*c.z + sgn*p.z*sn.z;
    o.w = x.w*c.w + sgn*p.w*sn.w;
    if (SCALE) { o.x *= 0.125f; o.y *= 0.125f; o.z *= 0.125f; o.w *= 0.125f; }
    __half2* dp = reinterpret_cast<__half2*>(&dst[((long)(b*NH + h)*SEQ + s)*HD + d0]);
    dp[0] = __floats2half2_rn(o.x, o.y);
    dp[1] = __floats2half2_rn(o.z, o.w);
}

// ---------------- V transpose (tiled): [B,S,H*D] -> [BH,D,S] fp16 -----------
__global__ __launch_bounds__(256)
void v_transpose_kernel(const float* __restrict__ src, __half* __restrict__ dst)
{
    __shared__ float t[32][33];
    const int bh = blockIdx.z;
    const int b = bh / NH, h = bh % NH;
    const int d0 = blockIdx.y * 32;
    const int s0 = blockIdx.x * 32;
    const int col = threadIdx.x & 31;
    const int rw  = threadIdx.x >> 5;
#pragma unroll
    for (int i = 0; i < 4; i++) {
        int row = rw + i*8;
        t[row][col] = src[(long)(b*SEQ + s0 + row)*EMB + h*HD + d0 + col];
    }
    __syncthreads();
#pragma unroll
    for (int i = 0; i < 4; i++) {
        int d = rw + i*8;
        dst[((long)bh*HD + d0 + d)*SEQ + s0 + col] = __float2half_rn(t[col][d]);
    }
}

// ---------------- TF32 pipelined GEMM: C = A@B^T (+bias)(+extra)(gelu) ----
template<int EPI, int BM, int BN, int WARPS_M, int WARPS_N>
__global__ __launch_bounds__(256)
void gemm_tf32(const float* __restrict__ A, const float* __restrict__ B,
               const float* __restrict__ bias, const float* __restrict__ extra,
               float* __restrict__ C,
               int K, int sAm, int sBn, int ldc)
{
    constexpr int BK   = 32;
    constexpr int LDSW = 36;
    constexpr int WM = BM / WARPS_M, WN = BN / WARPS_N;
    constexpr int MF = WM / 16, NF = WN / 8;
    constexpr int ASTG = BM * LDSW;
    constexpr int BSTG = BN * LDSW;

    extern __shared__ uint32_t smem[];
    uint32_t* As = smem;
    uint32_t* Bs = smem + 2 * ASTG;

    const int tid  = threadIdx.x;
    const int lane = tid & 31;
    const int warp = tid >> 5;
    const int wm = warp % WARPS_M, wn = warp / WARPS_M;
    const int row0 = blockIdx.y * BM, col0 = blockIdx.x * BN;
    A += (long)row0 * sAm;
    B += (long)col0 * sBn;

    const uint32_t smem_base = (uint32_t)__cvta_generic_to_shared(smem);
    const int r  = lane >> 2;
    const int cq = lane & 3;

    float acc[MF][NF][4];
#pragma unroll
    for (int m = 0; m < MF; m++)
#pragma unroll
        for (int n = 0; n < NF; n++)
#pragma unroll
            for (int j = 0; j < 4; j++) acc[m][n][j] = 0.f;

    const int lrow = tid >> 3;
    const int lf   = (tid & 7) * 4;

    auto prefetch = [&](int stage, int k0) {
#pragma unroll
        for (int i = 0; i < BM/32; i++) {
            int row = lrow + i*32;
            cp_async16(smem_base + (stage*ASTG + row*LDSW + lf)*4,
                       A + (long)row*sAm + k0 + lf);
        }
#pragma unroll
        for (int i = 0; i < BN/32; i++) {
            int row = lrow + i*32;
            cp_async16(smem_base + ((2*ASTG) + stage*BSTG + row*LDSW + lf)*4,
                       B + (long)row*sBn + k0 + lf);
        }
    };

    const int nk = K / BK;
    prefetch(0, 0);
    cp_commit();

    for (int kt = 0; kt < nk; kt++) {
        const int stage = kt & 1;
        if (kt + 1 < nk) prefetch(stage ^ 1, (kt+1) * BK);
        cp_commit();
        cp_wait1();
        __syncthreads();

        const uint32_t* Ast = As + stage * ASTG;
        const uint32_t* Bst = Bs + stage * BSTG;
#pragma unroll
        for (int ks = 0; ks < BK/8; ks++) {
            const int kk = ks * 8;
            uint32_t af[MF][4], bf[NF][2];
#pragma unroll
            for (int m = 0; m < MF; m++) {
                int base = (wm*WM + m*16 + r)*LDSW + kk + cq;
                af[m][0] = f2tf32(Ast[base]);
                af[m][1] = f2tf32(Ast[base + 8*LDSW]);
                af[m][2] = f2tf32(Ast[base + 4]);
                af[m][3] = f2tf32(Ast[base + 8*LDSW + 4]);
            }
#pragma unroll
            for (int n = 0; n < NF; n++) {
                int base = (wn*WN + n*8 + r)*LDSW + kk + cq;
                bf[n][0] = f2tf32(Bst[base]);
                bf[n][1] = f2tf32(Bst[base + 4]);
            }
#pragma unroll
            for (int m = 0; m < MF; m++)
#pragma unroll
                for (int n = 0; n < NF; n++)
                    mma_tf32(acc[m][n], af[m], bf[n]);
        }
        __syncthreads();
    }

#pragma unroll
    for (int m = 0; m < MF; m++) {
#pragma unroll
        for (int n = 0; n < NF; n++) {
            int row = row0 + wm*WM + m*16 + r;
            int col = col0 + wn*WN + n*8 + 2*cq;
            float v0 = acc[m][n][0];
            float v1 = acc[m][n][1];
            float v2 = acc[m][n][2];
            float v3 = acc[m][n][3];
            if (bias) { v0 += bias[col]; v1 += bias[col+1]; v2 += bias[col]; v3 += bias[col+1]; }
            if (EPI == 1) {
                v0 += extra[(long)row*ldc + col];
                v1 += extra[(long)row*ldc + col + 1];
                v2 += extra[(long)(row+8)*ldc + col];
                v3 += extra[(long)(row+8)*ldc + col + 1];
            }
            if (EPI == 2) {
                v0 = 0.5f * v0 * (1.f + erff(v0 * 0.70710678118654752f));
                v1 = 0.5f * v1 * (1.f + erff(v1 * 0.70710678118654752f));
                v2 = 0.5f * v2 * (1.f + erff(v2 * 0.70710678118654752f));
                v3 = 0.5f * v3 * (1.f + erff(v3 * 0.70710678118654752f));
            }
            *reinterpret_cast<float2*>(&C[(long)row*ldc + col])     = make_float2(v0, v1);
            *reinterpret_cast<float2*>(&C[(long)(row+8)*ldc + col]) = make_float2(v2, v3);
        }
    }
}

// ---------------- QK^T (fp16 MMA): E = exp(s/8) fp16 (coalesced) + sums -----
#define LDQ 72      // halfs per Q/K SMEM row
#define LDE 136     // halfs per Eh row
__global__ __launch_bounds__(256)
void qk_exp_kernel(const __half* __restrict__ qh, const __half* __restrict__ kh)
{
    extern __shared__ float sm[];
    __half* Qs = reinterpret_cast<__half*>(sm);     // [128*LDQ]
    __half* Ks = Qs + 128*LDQ;

    const int tid  = threadIdx.x;
    const int lane = tid & 31;
    const int warp = tid >> 5;
    const int wm = warp & 1, wn = warp >> 1;   // 2 x 4 warps: warp tile 64x32
    const int bh = blockIdx.z;
    const int row0 = blockIdx.y * 128, col0 = blockIdx.x * 128;
    const int r  = lane >> 2;
    const int cq = lane & 3;

    const __half* qb = qh + ((long)bh*SEQ + row0)*HD;
    const __half* kb = kh + ((long)bh*SEQ + col0)*HD;

    const uint32_t q_base = (uint32_t)__cvta_generic_to_shared(Qs);
    const uint32_t k_base = (uint32_t)__cvta_generic_to_shared(Ks);

#pragma unroll
    for (int i = 0; i < 4; i++) {
        int idx = tid + i*256;
        int row = idx >> 3, ch = (idx & 7) * 8;
        cp_async16(q_base + (row*LDQ + ch)*2, qb + (long)row*HD + ch);
        cp_async16(k_base + (row*LDQ + ch)*2, kb + (long)row*HD + ch);
    }
    cp_commit();
    cp_wait0();
    __syncthreads();

    float acc[4][4][4];
#pragma unroll
    for (int m = 0; m < 4; m++)
#pragma unroll
        for (int n = 0; n < 4; n++)
#pragma unroll
            for (int j = 0; j < 4; j++) acc[m][n][j] = 0.f;

#pragma unroll
    for (int ks = 0; ks < 4; ks++) {       // K=64 in 4 k16 steps
        const int kk = ks * 16;
        uint32_t af[4][4], bf[4][2];
#pragma unroll
        for (int m = 0; m < 4; m++) {
            int rowa = wm*64 + m*16 + r;
            af[m][0] = *reinterpret_cast<const uint32_t*>(&Qs[rowa*LDQ + kk + 2*cq]);
            af[m][1] = *reinterpret_cast<const uint32_t*>(&Qs[(rowa+8)*LDQ + kk + 2*cq]);
            af[m][2] = *reinterpret_cast<const uint32_t*>(&Qs[rowa*LDQ + kk + 2*cq + 8]);
            af[m][3] = *reinterpret_cast<const uint32_t*>(&Qs[(rowa+8)*LDQ + kk + 2*cq + 8]);
        }
#pragma unroll
        for (int n = 0; n < 4; n++) {
            int rowb = wn*32 + n*8 + r;
            bf[n][0] = *reinterpret_cast<const uint32_t*>(&Ks[rowb*LDQ + kk + 2*cq]);
            bf[n][1] = *reinterpret_cast<const uint32_t*>(&Ks[rowb*LDQ + kk + 2*cq + 8]);
        }
#pragma unroll
        for (int m = 0; m < 4; m++)
#pragma unroll
            for (int n = 0; n < 4; n++)
                mma_f16(acc[m][n], af[m], bf[n]);
    }

    // exp — the only exp pass in the whole pipeline (q pre-scaled by 1/8)
#pragma unroll
    for (int m = 0; m < 4; m++)
#pragma unroll
        for (int n = 0; n < 4; n++)
#pragma unroll
            for (int j = 0; j < 4; j++)
                acc[m][n][j] = __expf(acc[m][n][j]);

    // ---- stage E into SMEM (fp16) + partial sums ----
    __syncthreads();              // Qs/Ks dead; reuse as Eh + Sred
    __half* Eh = reinterpret_cast<__half*>(sm);         // [128][LDE]
    float* Sred = sm + (128*LDE)/2;                     // [128][17]
    const int slot = wn*4 + cq;

#pragma unroll
    for (int m = 0; m < 4; m++) {
#pragma unroll
        for (int n = 0; n < 4; n++) {
            int row = wm*64 + m*16 + r;
            int col = wn*32 + n*8 + 2*cq;
            *reinterpret_cast<__half2*>(&Eh[row*LDE + col]) =
                __floats2half2_rn(acc[m][n][0], acc[m][n][1]);
            *reinterpret_cast<__half2*>(&Eh[(row+8)*LDE + col]) =
                __floats2half2_rn(acc[m][n][2], acc[m][n][3]);
        }
    }
#pragma unroll
    for (int m = 0; m < 4; m++)
#pragma unroll
        for (int hf = 0; hf < 2; hf++) {
            int rl = wm*64 + m*16 + r + hf*8;
            float s = 0.f;
#pragma unroll
            for (int n = 0; n < 4; n++)
                s += acc[m][n][hf*2] + acc[m][n][hf*2+1];
            Sred[rl*17 + slot] = s;
        }
    __syncthreads();

    // ---- coalesced fp16 store: 2 threads per row ----
    __half* Eb = g_eh + (long)bh*SEQ*SEQ;
    {
        int row = tid >> 1;
        long gbase = (long)(row0 + row)*SEQ + col0;
#pragma unroll
        for (int j = 0; j < 8; j++) {
            int ho = ((tid & 1) + 2*j) * 8;
            uint4 v = *reinterpret_cast<const uint4*>(&Eh[row*LDE + ho]);
            __stcs(reinterpret_cast<uint4*>(Eb + gbase + ho), v);
        }
    }
    if (tid < 128) {
        float s = 0.f;
#pragma unroll
        for (int i = 0; i < 16; i++) s += Sred[tid*17 + i];
        g_psum[(long)(bh*16 + blockIdx.x)*SEQ + row0 + tid] = s;
    }
}

// ---------------- reduce 16 partials per row -> 1/sum ----------------
__global__ __launch_bounds__(256)
void reduce_stats_kernel()
{
    int rg = blockIdx.x * 256 + threadIdx.x;
    if (rg >= BH*SEQ) return;
    int bh = rg >> 11, row = rg & (SEQ-1);
    long base = (long)bh*16*SEQ + row;
    float s = 0.f;
#pragma unroll
    for (int i = 0; i < 16; i++) s += g_psum[base + (long)i*SEQ];
    g_rinv[rg] = 1.f / s;
}

// ---------------- AV (fp16 MMA on E, V^T): 3-stage, 1 sync/chunk ------------
#define AVLD 72   // halfs per SMEM row (64 + 8 pad)
__global__ __launch_bounds__(256)
void av_half_kernel(float* __restrict__ attn, float* __restrict__ vals)
{
    extern __shared__ float smf[];
    __half* Ah = reinterpret_cast<__half*>(smf);          // [3][64*AVLD]
    __half* Bh = Ah + 3*64*AVLD;                          // [3][64*AVLD]
    float*  rinv_s = smf + (6*64*AVLD)/2;                 // [64]

    const int tid  = threadIdx.x;
    const int lane = tid & 31;
    const int warp = tid >> 5;
    const int wm = warp & 1, wn = warp >> 1;   // 2 x 4 -> warp tile 32x16
    const int bh = blockIdx.z;
    const int b = bh / NH, h = bh % NH;
    const int row0 = blockIdx.y * 64;
    const int r  = lane >> 2;
    const int cq = lane & 3;

    const __half* Eb = g_eh + (long)bh*SEQ*SEQ + (long)row0*SEQ;
    const __half* Vb = g_vth + (long)bh*HD*SEQ;
    float* Ab = attn + (long)bh*SEQ*SEQ + (long)row0*SEQ;

    if (tid < 64) rinv_s[tid] = g_rinv[bh*SEQ + row0 + tid];

    const uint32_t a_base = (uint32_t)__cvta_generic_to_shared(Ah);
    const uint32_t b_base = (uint32_t)__cvta_generic_to_shared(Bh);

    auto prefetch = [&](int stage, int kc) {
#pragma unroll
        for (int i = 0; i < 2; i++) {
            int idx = tid + i*256;
            int row = idx >> 3, ch = (idx & 7) * 8;
            cp_async16(a_base + (stage*64*AVLD + row*AVLD + ch)*2,
                       Eb + (long)row*SEQ + kc*64 + ch);
            cp_async16(b_base + (stage*64*AVLD + row*AVLD + ch)*2,
                       Vb + (long)row*SEQ + kc*64 + ch);
        }
    };

    float acc[2][2][4];
#pragma unroll
    for (int m = 0; m < 2; m++)
#pragma unroll
        for (int n = 0; n < 2; n++)
#pragma unroll
            for (int j = 0; j < 4; j++) acc[m][n][j] = 0.f;

    prefetch(0, 0); cp_commit();
    prefetch(1, 1); cp_commit();

    for (int kt = 0; kt < 32; kt++) {
        const int stage = kt % 3;
        if (kt == 31) cp_wait0(); else cp_wait1();
        __syncthreads();            // single barrier per chunk (3-stage safe)

        const __half* Ast = Ah + stage*64*AVLD;
        const __half* Bst = Bh + stage*64*AVLD;

        // ---- coalesced prob store: 16 threads/row x float4 = 256B runs ----
#pragma unroll
        for (int g = 0; g < 4; g++) {
            int row  = g*16 + (tid >> 4);
            int colf = (tid & 15) * 4;
            __half2 h01 = *reinterpret_cast<const __half2*>(&Ast[row*AVLD + colf]);
            __half2 h23 = *reinterpret_cast<const __half2*>(&Ast[row*AVLD + colf + 2]);
            float riv = rinv_s[row];
            float4 o;
            o.x = __low2float(h01)  * riv;
            o.y = __high2float(h01) * riv;
            o.z = __low2float(h23)  * riv;
            o.w = __high2float(h23) * riv;
            __stcs(reinterpret_cast<float4*>(Ab + (long)row*SEQ + kt*64 + colf), o);
        }

        // ---- fp16 MMA on raw E / raw V ----
#pragma unroll
        for (int ks = 0; ks < 4; ks++) {
            const int kk = ks * 16;
            uint32_t af[2][4], bf[2][2];
#pragma unroll
            for (int m = 0; m < 2; m++) {
                int rowa = wm*32 + m*16 + r;
                af[m][0] = *reinterpret_cast<const uint32_t*>(&Ast[rowa*AVLD + kk + 2*cq]);
                af[m][1] = *reinterpret_cast<const uint32_t*>(&Ast[(rowa+8)*AVLD + kk + 2*cq]);
                af[m][2] = *reinterpret_cast<const uint32_t*>(&Ast[rowa*AVLD + kk + 2*cq + 8]);
                af[m][3] = *reinterpret_cast<const uint32_t*>(&Ast[(rowa+8)*AVLD + kk + 2*cq + 8]);
            }
#pragma unroll
            for (int n = 0; n < 2; n++) {
                int rowb = wn*16 + n*8 + r;
                bf[n][0] = *reinterpret_cast<const uint32_t*>(&Bst[rowb*AVLD + kk + 2*cq]);
                bf[n][1] = *reinterpret_cast<const uint32_t*>(&Bst[rowb*AVLD + kk + 2*cq + 8]);
            }
#pragma unroll
            for (int m = 0; m < 2; m++)
#pragma unroll
                for (int n = 0; n < 2; n++)
                    mma_f16(acc[m][n], af[m], bf[n]);
        }

        // prefetch 2 ahead (targets stage last used at kt-1; safe past top barrier)
        if (kt + 2 < 32) { prefetch((kt+2) % 3, kt + 2); cp_commit(); }
    }

    // epilogue: scale O rows by rinv, write merged [B,S,H*D]
#pragma unroll
    for (int m = 0; m < 2; m++) {
        int lr = wm*32 + m*16 + r;
        float s0 = rinv_s[lr], s1 = rinv_s[lr + 8];
#pragma unroll
        for (int n = 0; n < 2; n++) {
            int srow = row0 + lr;
            int col  = h*HD + wn*16 + n*8 + 2*cq;
            *reinterpret_cast<float2*>(&vals[(long)(b*SEQ + srow)*EMB + col]) =
                make_float2(acc[m][n][0]*s0, acc[m][n][1]*s0);
            *reinterpret_cast<float2*>(&vals[(long)(b*SEQ + srow + 8)*EMB + col]) =
                make_float2(acc[m][n][2]*s1, acc[m][n][3]*s1);
        }
    }
}

// ---------------- LayerNorm over 1280 (shfl reductions) ----------------
__global__ __launch_bounds__(256) void layernorm_kernel(const float* __restrict__ x,
    const float* __restrict__ g, const float* __restrict__ b, float* __restrict__ y)
{
    __shared__ float buf[PLMD];
    __shared__ float wred[8];
    long row = blockIdx.x;
    const float* xr = x + row*PLMD;
    int tid = threadIdx.x;
    int lane = tid & 31, warp = tid >> 5;

    float s = 0.f;
    for (int i = tid; i < PLMD; i += 256) { float t = xr[i]; buf[i] = t; s += t; }
#pragma unroll
    for (int o = 16; o > 0; o >>= 1) s += __shfl_xor_sync(0xffffffffu, s, o);
    if (lane == 0) wred[warp] = s;
    __syncthreads();
    float mu;
    {
        float t = wred[lane & 7];
#pragma unroll
        for (int o = 4; o > 0; o >>= 1) t += __shfl_xor_sync(0xffffffffu, t, o);
        mu = t * (1.f/PLMD);
    }
    float vs = 0.f;
    for (int i = tid; i < PLMD; i += 256) { float d = buf[i] - mu; vs += d*d; }
#pragma unroll
    for (int o = 16; o > 0; o >>= 1) vs += __shfl_xor_sync(0xffffffffu, vs, o);
    __syncthreads();
    if (lane == 0) wred[warp] = vs;
    __syncthreads();
    float rstd;
    {
        float t = wred[lane & 7];
#pragma unroll
        for (int o = 4; o > 0; o >>= 1) t += __shfl_xor_sync(0xffffffffu, t, o);
        rstd = rsqrtf(t * (1.f/PLMD) + 1e-5f);
    }
    float* yr = y + row*PLMD;
    for (int i = tid; i < PLMD; i += 256) yr[i] = (buf[i] - mu) * rstd * g[i] + b[i];
}

// ---------------- launch ----------------
extern "C" void kernel_launch(void* const* d_in, const int* in_sizes, int n_in,
                              void* d_out, int out_size)
{
    const float* s_repre = (const float*)d_in[0];
    const float* plm     = (const float*)d_in[1];
    const float* Wq = (const float*)d_in[2];  const float* bq = (const float*)d_in[3];
    const float* Wk = (const float*)d_in[4];  const float* bk = (const float*)d_in[5];
    const float* Wv = (const float*)d_in[6];  const float* bv = (const float*)d_in[7];
    const float* Wo = (const float*)d_in[8];  const float* bo = (const float*)d_in[9];
    const float* lng = (const float*)d_in[10]; const float* lnb = (const float*)d_in[11];
    const float* Wd = (const float*)d_in[12]; const float* bd = (const float*)d_in[13];
    const float* Wu = (const float*)d_in[14]; const float* bu = (const float*)d_in[15];

    float* out  = (float*)d_out;
    float* attn = out + OUT_ELEMS;   // tuple order: (out, attention)

    float *qp,*kp,*vp,*vals,*x,*ln,*ff;
    __half *qh,*kh,*vth;
    cudaGetSymbolAddress((void**)&qp, g_qp);
    cudaGetSymbolAddress((void**)&kp, g_kp);
    cudaGetSymbolAddress((void**)&vp, g_vp);
    cudaGetSymbolAddress((void**)&qh, g_qh);
    cudaGetSymbolAddress((void**)&kh, g_kh);
    cudaGetSymbolAddress((void**)&vth, g_vth);
    cudaGetSymbolAddress((void**)&vals, g_vals);
    cudaGetSymbolAddress((void**)&x, g_x);
    cudaGetSymbolAddress((void**)&ln, g_ln);
    cudaGetSymbolAddress((void**)&ff, g_ff);

    const int S_128_128 = 2 * (128 + 128) * 36 * 4;        // 73728
    const int S_QK  = 128*LDE*2 + 128*17*4;                // 43520
    const int S_AV  = 6*64*AVLD*2 + 64*4;                  // 55552
    cudaFuncSetAttribute(gemm_tf32<0,128,128,2,4>, cudaFuncAttributeMaxDynamicSharedMemorySize, S_128_128);
    cudaFuncSetAttribute(gemm_tf32<1,128,128,2,4>, cudaFuncAttributeMaxDynamicSharedMemorySize, S_128_128);
    cudaFuncSetAttribute(gemm_tf32<2,128,128,2,4>, cudaFuncAttributeMaxDynamicSharedMemorySize, S_128_128);
    cudaFuncSetAttribute(qk_exp_kernel, cudaFuncAttributeMaxDynamicSharedMemorySize, S_QK);
    cudaFuncSetAttribute(av_half_kernel, cudaFuncAttributeMaxDynamicSharedMemorySize, S_AV);

    rope_table_kernel<<<(SEQ*32 + 255)/256, 256>>>();

    // QKV projections
    gemm_tf32<0,128,128,2,4><<<dim3(EMB/128, ROWS/128, 1), 256, S_128_128>>>(
        plm, Wq, bq, nullptr, qp, PLMD, PLMD, PLMD, EMB);
    gemm_tf32<0,128,128,2,4><<<dim3(EMB/128, ROWS/128, 1), 256, S_128_128>>>(
        s_repre, Wk, bk, nullptr, kp, SD, SD, SD, EMB);
    gemm_tf32<0,128,128,2,4><<<dim3(EMB/128, ROWS/128, 1), 256, S_128_128>>>(
        s_repre, Wv, bv, nullptr, vp, SD, SD, SD, EMB);

    // rope -> fp16 [BH,S,D] (q pre-scaled), V transpose -> fp16 [BH,D,S]
    rope_apply_kernel<true ><<<(ROWS*EMB/4 + 255)/256, 256>>>(qp, qh);
    rope_apply_kernel<false><<<(ROWS*EMB/4 + 255)/256, 256>>>(kp, kh);
    v_transpose_kernel<<<dim3(SEQ/32, HD/32, BH), 256>>>(vp, vth);

    // exp(QK^T/8) fp16 MMA -> g_eh (fp16, coalesced) + partial sums
    qk_exp_kernel<<<dim3(SEQ/128, SEQ/128, BH), 256, S_QK>>>(qh, kh);

    // finalize 1/rowsum
    reduce_stats_kernel<<<(BH*SEQ + 255)/256, 256>>>();

    // AV fp16 MMA: probs (fp32, once) -> d_out, O*rinv -> merged vals
    av_half_kernel<<<dim3(1, SEQ/64, BH), 256, S_AV>>>(attn, vals);

    // o = vals @ Wo^T + bo + plm (residual fused)
    gemm_tf32<1,128,128,2,4><<<dim3(PLMD/128, ROWS/128, 1), 256, S_128_128>>>(
        vals, Wo, bo, plm, x, EMB, EMB, EMB, PLMD);

    layernorm_kernel<<<ROWS, 256>>>(x, lng, lnb, ln);

    gemm_tf32<2,128,128,2,4><<<dim3(FFD/128, ROWS/128, 1), 256, S_128_128>>>(
        ln, Wd, bd, nullptr, ff, PLMD, PLMD, PLMD, FFD);

    gemm_tf32<1,128,128,2,4><<<dim3(PLMD/128, ROWS/128, 1), 256, S_128_128>>>(
        ff, Wu, bu, ln, out, FFD, FFD, FFD, PLMD);
}